// round 12
// baseline (speedup 1.0000x reference)
#include <cuda_runtime.h>
#include <cuda_bf16.h>
#include <math.h>

// ---------------- problem constants ----------------
#define BN     16      // batch
#define CIN    16      // input channels
#define HIN    224
#define WIN    224
#define MID    128
#define HW0    (HIN*WIN)   // 50176

// ---------------- scratch (device globals; no allocation) ----------------
__device__ float g_act0[(size_t)BN*MID*224*224];   // conv0 raw output
__device__ float g_conv[(size_t)BN*MID*222*222];   // conv3x3 raw output (max size)
__device__ float g_pa  [(size_t)BN*MID*110*110];   // pooled ping
__device__ float g_pb  [(size_t)BN*MID*53*53];     // pooled pong
__device__ float g_V   [(size_t)BN*MID*16*12544];  // winograd V, [n][ci][k][tile]
__device__ float g_U   [MID*16*MID];               // winograd U, [ci][k][co]
__device__ float  g_alpha[MID];
__device__ float  g_beta [MID];
__device__ double g_bnp [MID*8*2];                 // BN partial sums
__device__ float  g_feat[BN*2048];
__device__ double g_reg [BN*7];
__device__ double g_theta[BN*6];
__device__ double g_m[BN];

__device__ __forceinline__ float* getbuf(int s) {
    switch (s) {
        case 0: return g_act0;
        case 1: return g_conv;
        case 2: return g_pa;
        default: return g_pb;
    }
}

// ---------------- conv0: 1x1, 16 -> 128 ----------------
__global__ __launch_bounds__(256) void k_conv0(const float* __restrict__ x,
                                               const float* __restrict__ w,
                                               const float* __restrict__ b) {
    __shared__ float ws[MID*CIN];
    __shared__ float bs[MID];
    int tid = threadIdx.x;
    for (int i = tid; i < MID*CIN; i += 256) ws[i] = w[i];
    if (tid < MID) bs[tid] = b[tid];
    __syncthreads();

    long gid = (long)blockIdx.x * 256 + tid;             // pixel-group id
    int n  = (int)(gid / (HW0/4));
    int pg = (int)(gid % (HW0/4));
    int p  = pg * 4;

    const float* xp = x + (long)n*CIN*HW0 + p;
    float4 v[CIN];
    #pragma unroll
    for (int ci = 0; ci < CIN; ci++)
        v[ci] = *(const float4*)(xp + (long)ci*HW0);

    float* op = g_act0 + (long)n*MID*HW0 + p;
    for (int co = 0; co < MID; co++) {
        float4 a; a.x = a.y = a.z = a.w = bs[co];
        #pragma unroll
        for (int ci = 0; ci < CIN; ci++) {
            float wv = ws[co*CIN + ci];
            a.x = fmaf(v[ci].x, wv, a.x);
            a.y = fmaf(v[ci].y, wv, a.y);
            a.z = fmaf(v[ci].z, wv, a.z);
            a.w = fmaf(v[ci].w, wv, a.w);
        }
        *(float4*)(op + (long)co*HW0) = a;
    }
}

// ---------------- BN stats: 8-way split partials + fixed-order finalize -----
__global__ void k_bn_part(int inbuf, int HWp) {
    int c = blockIdx.x & 127;
    int p = blockIdx.x >> 7;                 // 0..7 -> images [2p, 2p+2)
    const float* base0 = getbuf(inbuf);
    int tid = threadIdx.x;
    double s = 0.0, ss = 0.0;
    for (int n = p*2; n < p*2 + 2; n++) {
        const float* base = base0 + ((long)n*MID + c) * HWp;
        for (int i = tid; i < HWp; i += 256) {
            double v = (double)base[i];
            s += v; ss += v*v;
        }
    }
    __shared__ double sh[256], sh2[256];
    sh[tid] = s; sh2[tid] = ss;
    __syncthreads();
    for (int k = 128; k > 0; k >>= 1) {
        if (tid < k) { sh[tid] += sh[tid+k]; sh2[tid] += sh2[tid+k]; }
        __syncthreads();
    }
    if (tid == 0) {
        g_bnp[(c*8 + p)*2    ] = sh[0];
        g_bnp[(c*8 + p)*2 + 1] = sh2[0];
    }
}

__global__ void k_bn_fin(int HWp, const float* __restrict__ g,
                         const float* __restrict__ b) {
    int c = threadIdx.x;                     // 128 threads
    double s = 0.0, ss = 0.0;
    for (int p = 0; p < 8; p++) {            // fixed order -> deterministic
        s  += g_bnp[(c*8 + p)*2];
        ss += g_bnp[(c*8 + p)*2 + 1];
    }
    double M   = (double)BN * (double)HWp;
    double mu  = s / M;
    double var = ss / M - mu*mu;
    double a   = (double)g[c] / sqrt(var + 1e-5);
    g_alpha[c] = (float)a;
    g_beta[c]  = (float)((double)b[c] - mu*a);
}

// ---------------- winograd weight transform: U[ci][k][co] = G g G^T --------
__global__ void k_ugen(const float* __restrict__ w) {
    int idx = blockIdx.x*256 + threadIdx.x;
    if (idx >= MID*MID) return;
    int co = idx & 127, ci = idx >> 7;
    float g[3][3];
    #pragma unroll
    for (int r = 0; r < 3; r++)
        #pragma unroll
        for (int c = 0; c < 3; c++)
            g[r][c] = w[((long)(co*MID + ci)*3 + r)*3 + c];
    float t[4][3];
    #pragma unroll
    for (int c = 0; c < 3; c++) {
        t[0][c] = g[0][c];
        t[1][c] = 0.5f*(g[0][c] + g[1][c] + g[2][c]);
        t[2][c] = 0.5f*(g[0][c] - g[1][c] + g[2][c]);
        t[3][c] = g[2][c];
    }
    float* out = g_U + (long)ci*16*MID + co;
    #pragma unroll
    for (int r = 0; r < 4; r++) {
        float u0 = t[r][0];
        float u1 = 0.5f*(t[r][0] + t[r][1] + t[r][2]);
        float u2 = 0.5f*(t[r][0] - t[r][1] + t[r][2]);
        float u3 = t[r][2];
        out[(r*4+0)*MID] = u0;
        out[(r*4+1)*MID] = u1;
        out[(r*4+2)*MID] = u2;
        out[(r*4+3)*MID] = u3;
    }
}

// ---------------- winograd input transform: V = B^T d B (with BN+ReLU) -----
// g_V layout: [n][ci][k][tile]; tile = ty*TP+tx, plane stride TP*TP
__global__ void k_vgen(int inbuf, int HI, int WI, int TP, long total) {
    long idx = (long)blockIdx.x*256 + threadIdx.x;
    if (idx >= total) return;
    long q = idx;
    int tx = (int)(q % TP); q /= TP;
    int ty = (int)(q % TP); q /= TP;
    int ci = (int)(q & 127);
    int n  = (int)(q >> 7);
    const float* in = getbuf(inbuf) + (long)(n*MID + ci)*HI*WI;
    float al = g_alpha[ci], be = g_beta[ci];

    float d[4][4];
    int iy0 = ty*2, ix0 = tx*2;
    #pragma unroll
    for (int r = 0; r < 4; r++) {
        int iy = iy0 + r;
        #pragma unroll
        for (int c = 0; c < 4; c++) {
            int ix = ix0 + c;
            float v = 0.f;
            if (iy < HI && ix < WI) v = in[iy*WI + ix];
            d[r][c] = fmaxf(fmaf(al, v, be), 0.f);
        }
    }
    // t = B^T d
    float t0[4], t1[4], t2[4], t3[4];
    #pragma unroll
    for (int c = 0; c < 4; c++) {
        t0[c] = d[0][c] - d[2][c];
        t1[c] = d[1][c] + d[2][c];
        t2[c] = d[2][c] - d[1][c];
        t3[c] = d[1][c] - d[3][c];
    }
    long TP2 = (long)TP*TP;
    float* out = g_V + ((long)(n*MID + ci)*16)*TP2 + (long)ty*TP + tx;
    float* rows[4] = {t0, t1, t2, t3};
    #pragma unroll
    for (int r = 0; r < 4; r++) {
        float* a = rows[r];
        out[(long)(r*4+0)*TP2] = a[0] - a[2];
        out[(long)(r*4+1)*TP2] = a[1] + a[2];
        out[(long)(r*4+2)*TP2] = a[2] - a[1];
        out[(long)(r*4+3)*TP2] = a[1] - a[3];
    }
}

// ---------------- winograd multiply + output transform (fp32) --------------
// block: 256 thr = 16 k-points x 16 workers; worker = 8co x 4tiles at one k.
// block tile: 16k x 32co x 16tiles (linear). 16-ci chunks (8 chunks),
// 2-stage cp.async pipeline, proven wait -> bar -> compute -> bar structure.
// fp32 chunk accumulation (16 ci) + fp32 fold (8 chunks).
__global__ __launch_bounds__(256)
void k_wino(int HO, int WO, int TP, const float* __restrict__ bias) {
    extern __shared__ __align__(16) float sm[];   // 2 x 12288 floats = 96 KB

    int tid = threadIdx.x;
    int kk = tid >> 4, w = tid & 15, cb = w >> 2, tb = w & 3;
    int tg0 = blockIdx.y << 4;          // 16 tiles per block
    int n   = blockIdx.z;
    int co0 = blockIdx.x << 5;

    unsigned smb = (unsigned)__cvta_generic_to_shared(sm);
    long TP2 = (long)TP*TP;

    auto issue_chunk = [&](int c) {
        int ci0 = c*16;
        unsigned vb = smb + (unsigned)((c&1)*12288)*4u;
        unsigned ub = vb + 4096u*4u;
        // V: 16ci x 16k x 16tiles = 1024 float4, 4/thread
        #pragma unroll
        for (int it = 0; it < 4; it++) {
            int u = tid + it*256;
            int f4 = u & 3, k = (u>>2)&15, ci = u>>6;
            const float* src = g_V + ((long)(n*MID + ci0+ci)*16 + k)*TP2
                                   + tg0 + f4*4;
            unsigned dst = vb + (unsigned)((ci*16+k)*16 + f4*4)*4u;
            asm volatile("cp.async.ca.shared.global [%0], [%1], 16;\n"
                         :: "r"(dst), "l"(src));
        }
        // U: 16ci x 16k x 32co = 2048 float4, 8/thread
        #pragma unroll
        for (int it = 0; it < 8; it++) {
            int u = tid + it*256;
            int f4 = u & 7, k = (u>>3)&15, ci = u>>7;
            const float* src = g_U + ((long)(ci0+ci)*16 + k)*MID + co0 + f4*4;
            unsigned dst = ub + (unsigned)((ci*16+k)*32 + f4*4)*4u;
            asm volatile("cp.async.ca.shared.global [%0], [%1], 16;\n"
                         :: "r"(dst), "l"(src));
        }
        asm volatile("cp.async.commit_group;\n");
    };

    float macc[8][4];
    #pragma unroll
    for (int i = 0; i < 8; i++)
        #pragma unroll
        for (int t = 0; t < 4; t++) macc[i][t] = 0.f;

    issue_chunk(0);

    #pragma unroll 1
    for (int c = 0; c < 8; c++) {
        // issue into buf (c+1)&1 == (c-1)&1: freed by trailing barrier of c-1
        if (c + 1 < 8) {
            issue_chunk(c + 1);
            asm volatile("cp.async.wait_group 1;\n");   // chunk c complete (own)
        } else {
            asm volatile("cp.async.wait_group 0;\n");
        }
        __syncthreads();     // cross-thread visibility of chunk c

        const float* Vb = sm + (c&1)*12288;
        const float* Ub = Vb + 4096;

        float acc[8][4];
        #pragma unroll
        for (int i = 0; i < 8; i++)
            #pragma unroll
            for (int t = 0; t < 4; t++) acc[i][t] = 0.f;

        #pragma unroll
        for (int ci = 0; ci < 16; ci++) {
            float4 v  = *(const float4*)(Vb + (ci*16+kk)*16 + tb*4);
            float4 ua = *(const float4*)(Ub + (ci*16+kk)*32 + cb*8);
            float4 uc = *(const float4*)(Ub + (ci*16+kk)*32 + cb*8 + 4);
            float vv[4] = {v.x, v.y, v.z, v.w};
            float uu[8] = {ua.x, ua.y, ua.z, ua.w, uc.x, uc.y, uc.z, uc.w};
            #pragma unroll
            for (int i = 0; i < 8; i++)
                #pragma unroll
                for (int t = 0; t < 4; t++)
                    acc[i][t] = fmaf(uu[i], vv[t], acc[i][t]);
        }
        #pragma unroll
        for (int i = 0; i < 8; i++)
            #pragma unroll
            for (int t = 0; t < 4; t++) macc[i][t] += acc[i][t];

        __syncthreads();     // compute(c) done before buf (c)&1 is overwritten
    }

    // ---- epilogue: 2 passes over co halves; transpose via smem ----
    #pragma unroll
    for (int p = 0; p < 2; p++) {
        __syncthreads();
        if ((cb >> 1) == p) {
            int coh = (cb & 1)*8;
            #pragma unroll
            for (int i = 0; i < 8; i++)
                #pragma unroll
                for (int t = 0; t < 4; t++)
                    sm[kk*256 + (coh+i)*16 + tb*4 + t] = macc[i][t];
        }
        __syncthreads();

        int coL = tid >> 4;          // 0..15
        int til = tid & 15;
        float m[16];
        #pragma unroll
        for (int k = 0; k < 16; k++)
            m[k] = sm[k*256 + coL*16 + til];

        float t0[4], t1[4];
        #pragma unroll
        for (int c = 0; c < 4; c++) {
            t0[c] = m[c] + m[4+c] + m[8+c];
            t1[c] = m[4+c] - m[8+c] - m[12+c];
        }
        int co = co0 + p*16 + coL;
        float bv = bias[co];
        float y00 = t0[0] + t0[1] + t0[2] + bv;
        float y01 = t0[1] - t0[2] - t0[3] + bv;
        float y10 = t1[0] + t1[1] + t1[2] + bv;
        float y11 = t1[1] - t1[2] - t1[3] + bv;

        int tgl = tg0 + til;
        int ty = tgl / TP, tx = tgl - ty*TP;
        int oy = ty*2, ox = tx*2;
        float* out = g_conv + (long)(n*MID + co)*HO*WO;
        if (oy < HO) {
            if (ox   < WO) out[oy*WO + ox  ] = y00;
            if (ox+1 < WO) out[oy*WO + ox+1] = y01;
        }
        if (oy+1 < HO) {
            if (ox   < WO) out[(oy+1)*WO + ox  ] = y10;
            if (ox+1 < WO) out[(oy+1)*WO + ox+1] = y11;
        }
    }
}

// ---------------- maxpool 3x3 stride 2 (valid) ----------------
__global__ void k_pool(int outbuf, int HO, int WO, int HP, int WP) {
    const float* in = g_conv;
    float* out = getbuf(outbuf);
    long idx = (long)blockIdx.x * 256 + threadIdx.x;
    long total = (long)BN * MID * HP * WP;
    if (idx >= total) return;
    int wp = (int)(idx % WP); long t = idx / WP;
    int hp = (int)(t % HP);   t /= HP;        // t = n*128 + c
    const float* base = in + t * (long)HO * WO + (long)(hp*2) * WO + wp*2;
    float m = -3.4e38f;
    #pragma unroll
    for (int a = 0; a < 3; a++)
        #pragma unroll
        for (int b2 = 0; b2 < 3; b2++)
            m = fmaxf(m, base[a*WO + b2]);
    out[idx] = m;
}

// ---------------- LRN (size=128 channel window) after BN+ReLU, fp64 --------
__global__ void k_lrn(int inbuf) {
    const float* in = getbuf(inbuf);
    int blk = blockIdx.x;
    int n = blk >> 4, hw = blk & 15;
    int c = threadIdx.x;
    __shared__ double sq[MID];
    float vf = in[(((long)n*MID + c) * 16) + hw];
    double v = fmax(fma((double)g_alpha[c], (double)vf, (double)g_beta[c]), 0.0);
    sq[c] = v * v;
    __syncthreads();
    int lo = c - 64 < 0 ? 0 : c - 64;
    int hi = c + 63 > 127 ? 127 : c + 63;
    double wsum = 0.0;
    for (int j = lo; j <= hi; j++) wsum += sq[j];
    double base = 1.0 + 1e-4 * (wsum / 128.0);
    g_feat[n*2048 + c*16 + hw] = (float)(v * pow(base, -0.75));
}

// ---------------- linear: reg = feat @ Wr^T + br  (fp64 accum) -------------
__global__ void k_linear(const float* __restrict__ Wr, const float* __restrict__ br) {
    int j = blockIdx.x % 7, n = blockIdx.x / 7;
    const float* f  = g_feat + n*2048;
    const float* wr = Wr + j*2048;
    double s = 0.0;
    for (int k = threadIdx.x; k < 2048; k += 32)
        s += (double)f[k] * (double)wr[k];
    #pragma unroll
    for (int o = 16; o > 0; o >>= 1)
        s += __shfl_down_sync(0xffffffffu, s, o);
    if (threadIdx.x == 0) g_reg[n*7 + j] = s + (double)br[j];
}

// ---------------- spectral normalize (sequential scan, fp64) + sigmoid -----
__global__ void k_spectral(const float* __restrict__ u0, const float* __restrict__ v0) {
    double u[2] = {(double)u0[0], (double)u0[1]};
    double v[3] = {(double)v0[0], (double)v0[1], (double)v0[2]};
    for (int n = 0; n < BN; n++) {
        double W[6];
        #pragma unroll
        for (int i = 0; i < 6; i++) W[i] = g_reg[n*7 + i];
        for (int it = 0; it < 4; it++) {
            double nv0 = W[0]*u[0] + W[3]*u[1];
            double nv1 = W[1]*u[0] + W[4]*u[1];
            double nv2 = W[2]*u[0] + W[5]*u[1];
            double nn = sqrt(nv0*nv0 + nv1*nv1 + nv2*nv2);
            nn = fmax(nn, 1e-12);
            v[0] = nv0/nn; v[1] = nv1/nn; v[2] = nv2/nn;
            double nu0 = W[0]*v[0] + W[1]*v[1] + W[2]*v[2];
            double nu1 = W[3]*v[0] + W[4]*v[1] + W[5]*v[2];
            nn = sqrt(nu0*nu0 + nu1*nu1);
            nn = fmax(nn, 1e-12);
            u[0] = nu0/nn; u[1] = nu1/nn;
        }
        double Wv0 = W[0]*v[0] + W[1]*v[1] + W[2]*v[2];
        double Wv1 = W[3]*v[0] + W[4]*v[1] + W[5]*v[2];
        double sigma = u[0]*Wv0 + u[1]*Wv1;
        #pragma unroll
        for (int i = 0; i < 6; i++) g_theta[n*6 + i] = W[i] / sigma;
        g_m[n] = 1.0 / (1.0 + exp(-g_reg[n*7 + 6]));
    }
}

// ---------------- affine grid + reflect bilinear sample + scale ------------
__device__ __forceinline__ double reflect_d(double x, double size) {
    double r = fabs(x + 0.5);
    r = fmod(r, 2.0 * size);
    if (r > size) r = 2.0 * size - r;
    r = r - 0.5;
    return fmin(fmax(r, 0.0), size - 1.0);
}

__global__ void k_sample(const float* __restrict__ x, float* __restrict__ out) {
    long idx = (long)blockIdx.x * 256 + threadIdx.x;    // over N*H*W
    if (idx >= (long)BN * HW0) return;
    int w = (int)(idx % WIN); long t = idx / WIN;
    int h = (int)(t % HIN);
    int n = (int)(t / HIN);

    const double* th = g_theta + n*6;
    double gx = (2.0*w + 1.0) / (double)WIN - 1.0;
    double gy = (2.0*h + 1.0) / (double)HIN - 1.0;
    double px = th[0]*gx + th[1]*gy + th[2];
    double py = th[3]*gx + th[4]*gy + th[5];

    double ix = reflect_d(((px + 1.0) * (double)WIN - 1.0) * 0.5, (double)WIN);
    double iy = reflect_d(((py + 1.0) * (double)HIN - 1.0) * 0.5, (double)HIN);

    double x0f = floor(ix), y0f = floor(iy);
    double wx = ix - x0f, wy = iy - y0f;
    int x0i = min(max((int)x0f, 0), WIN-1);
    int y0i = min(max((int)y0f, 0), HIN-1);
    int x1i = min(max((int)x0f + 1, 0), WIN-1);
    int y1i = min(max((int)y0f + 1, 0), HIN-1);

    double w00 = (1.0-wx)*(1.0-wy), w01 = wx*(1.0-wy);
    double w10 = (1.0-wx)*wy,       w11 = wx*wy;
    double mm = g_m[n];

    const float* xb = x   + (long)n*CIN*HW0;
    float*       ob = out + (long)n*CIN*HW0 + (long)h*WIN + w;
    int o00 = y0i*WIN + x0i, o01 = y0i*WIN + x1i;
    int o10 = y1i*WIN + x0i, o11 = y1i*WIN + x1i;
    for (int c = 0; c < CIN; c++) {
        const float* xc = xb + (long)c*HW0;
        double v = (double)xc[o00]*w00 + (double)xc[o01]*w01
                 + (double)xc[o10]*w10 + (double)xc[o11]*w11;
        ob[(long)c*HW0] = (float)(v * mm);
    }
}

// ---------------- host orchestration ----------------
extern "C" void kernel_launch(void* const* d_in, const int* in_sizes, int n_in,
                              void* d_out, int out_size) {
    const float* x       = (const float*)d_in[0];
    const float* conv0_w = (const float*)d_in[1];
    const float* conv0_b = (const float*)d_in[2];
    const float* convs_w = (const float*)d_in[3];
    const float* convs_b = (const float*)d_in[4];
    const float* bn_g    = (const float*)d_in[5];
    const float* bn_b    = (const float*)d_in[6];
    const float* Wr      = (const float*)d_in[7];
    const float* br      = (const float*)d_in[8];
    const float* u0      = (const float*)d_in[9];
    const float* v0      = (const float*)d_in[10];
    float* out = (float*)d_out;

    // allow 96 KB dynamic smem for k_wino (host-side attr, capture-safe)
    cudaFuncSetAttribute(k_wino, cudaFuncAttributeMaxDynamicSharedMemorySize, 98304);

    // conv0 (1x1) -> g_act0 (buf 0)
    k_conv0<<<(BN*HW0/4 + 255)/256, 256>>>(x, conv0_w, conv0_b);
    // bn0 stats on conv0 output
    k_bn_part<<<1024, 256>>>(0, HW0);
    k_bn_fin<<<1, 128>>>(HW0, bn_g + 0*MID, bn_b + 0*MID);

    struct Stage { int inbuf, outbuf, HI, HO, HP, TP; };
    const Stage st[5] = {
        {0, 2, 224, 222, 110, 112},
        {2, 3, 110, 108,  53,  56},
        {3, 2,  53,  51,  25,  28},
        {2, 3,  25,  23,  11,  12},
        {3, 2,  11,   9,   4,   8},
    };

    for (int s = 0; s < 5; s++) {
        int HI = st[s].HI, HO = st[s].HO, HP = st[s].HP, TP = st[s].TP;
        // weight transform
        k_ugen<<<(MID*MID + 255)/256, 256>>>(convs_w + (size_t)s*MID*MID*9);
        // input transform (fused BN+ReLU)
        long vtotal = (long)BN * MID * TP * TP;
        k_vgen<<<(unsigned)((vtotal + 255)/256), 256>>>(st[s].inbuf, HI, HI, TP, vtotal);
        // winograd multiply + output transform -> g_conv
        dim3 wgrid(4, (TP*TP)/16, BN);
        k_wino<<<wgrid, 256, 98304>>>(HO, HO, TP, convs_b + s*MID);
        // maxpool + next BN stats
        long ptotal = (long)BN*MID*HP*HP;
        k_pool<<<(unsigned)((ptotal + 255)/256), 256>>>(st[s].outbuf, HO, HO, HP, HP);
        k_bn_part<<<1024, 256>>>(st[s].outbuf, HP*HP);
        k_bn_fin<<<1, 128>>>(HP*HP, bn_g + (s+1)*MID, bn_b + (s+1)*MID);
    }

    // LRN on final pooled (buf 2 = g_pa, 16x128x4x4) with bn5 transform
    k_lrn<<<BN*16, MID>>>(2);
    // linear -> reg
    k_linear<<<BN*7, 32>>>(Wr, br);
    // spectral norm scan + m
    k_spectral<<<1, 1>>>(u0, v0);
    // sample
    k_sample<<<(unsigned)(((long)BN*HW0 + 255)/256), 256>>>(x, out);
}

// round 13
// speedup vs baseline: 1.0529x; 1.0529x over previous
#include <cuda_runtime.h>
#include <cuda_bf16.h>
#include <math.h>

// ---------------- problem constants ----------------
#define BN     16      // batch
#define CIN    16      // input channels
#define HIN    224
#define WIN    224
#define MID    128
#define HW0    (HIN*WIN)   // 50176

// ---------------- scratch (device globals; no allocation) ----------------
__device__ float g_act0[(size_t)BN*MID*224*224];   // conv0 raw output
__device__ float g_conv[(size_t)BN*MID*222*222];   // conv3x3 raw output (max size)
__device__ float g_pa  [(size_t)BN*MID*110*110];   // pooled ping
__device__ float g_pb  [(size_t)BN*MID*53*53];     // pooled pong
__device__ float g_V   [(size_t)BN*MID*16*12544];  // winograd V, [n][ci][k][tile]
__device__ float g_U   [MID*16*MID];               // winograd U, [ci][k][co]
__device__ float  g_alpha[MID];
__device__ float  g_beta [MID];
__device__ double g_bnp [MID*8*2];                 // BN partial sums
__device__ float  g_feat[BN*2048];
__device__ double g_reg [BN*7];
__device__ double g_theta[BN*6];
__device__ double g_m[BN];

__device__ __forceinline__ float* getbuf(int s) {
    switch (s) {
        case 0: return g_act0;
        case 1: return g_conv;
        case 2: return g_pa;
        default: return g_pb;
    }
}

// ---------------- conv0: 1x1, 16 -> 128 ----------------
__global__ __launch_bounds__(256) void k_conv0(const float* __restrict__ x,
                                               const float* __restrict__ w,
                                               const float* __restrict__ b) {
    __shared__ float ws[MID*CIN];
    __shared__ float bs[MID];
    int tid = threadIdx.x;
    for (int i = tid; i < MID*CIN; i += 256) ws[i] = w[i];
    if (tid < MID) bs[tid] = b[tid];
    __syncthreads();

    long gid = (long)blockIdx.x * 256 + tid;             // pixel-group id
    int n  = (int)(gid / (HW0/4));
    int pg = (int)(gid % (HW0/4));
    int p  = pg * 4;

    const float* xp = x + (long)n*CIN*HW0 + p;
    float4 v[CIN];
    #pragma unroll
    for (int ci = 0; ci < CIN; ci++)
        v[ci] = *(const float4*)(xp + (long)ci*HW0);

    float* op = g_act0 + (long)n*MID*HW0 + p;
    for (int co = 0; co < MID; co++) {
        float4 a; a.x = a.y = a.z = a.w = bs[co];
        #pragma unroll
        for (int ci = 0; ci < CIN; ci++) {
            float wv = ws[co*CIN + ci];
            a.x = fmaf(v[ci].x, wv, a.x);
            a.y = fmaf(v[ci].y, wv, a.y);
            a.z = fmaf(v[ci].z, wv, a.z);
            a.w = fmaf(v[ci].w, wv, a.w);
        }
        *(float4*)(op + (long)co*HW0) = a;
    }
}

// ---------------- BN stats: 8-way split partials + fixed-order finalize -----
__global__ void k_bn_part(int inbuf, int HWp) {
    int c = blockIdx.x & 127;
    int p = blockIdx.x >> 7;                 // 0..7 -> images [2p, 2p+2)
    const float* base0 = getbuf(inbuf);
    int tid = threadIdx.x;
    double s = 0.0, ss = 0.0;
    for (int n = p*2; n < p*2 + 2; n++) {
        const float* base = base0 + ((long)n*MID + c) * HWp;
        for (int i = tid; i < HWp; i += 256) {
            double v = (double)base[i];
            s += v; ss += v*v;
        }
    }
    __shared__ double sh[256], sh2[256];
    sh[tid] = s; sh2[tid] = ss;
    __syncthreads();
    for (int k = 128; k > 0; k >>= 1) {
        if (tid < k) { sh[tid] += sh[tid+k]; sh2[tid] += sh2[tid+k]; }
        __syncthreads();
    }
    if (tid == 0) {
        g_bnp[(c*8 + p)*2    ] = sh[0];
        g_bnp[(c*8 + p)*2 + 1] = sh2[0];
    }
}

__global__ void k_bn_fin(int HWp, const float* __restrict__ g,
                         const float* __restrict__ b) {
    int c = threadIdx.x;                     // 128 threads
    double s = 0.0, ss = 0.0;
    for (int p = 0; p < 8; p++) {            // fixed order -> deterministic
        s  += g_bnp[(c*8 + p)*2];
        ss += g_bnp[(c*8 + p)*2 + 1];
    }
    double M   = (double)BN * (double)HWp;
    double mu  = s / M;
    double var = ss / M - mu*mu;
    double a   = (double)g[c] / sqrt(var + 1e-5);
    g_alpha[c] = (float)a;
    g_beta[c]  = (float)((double)b[c] - mu*a);
}

// ---------------- winograd weight transform: U[ci][k][co] = G g G^T --------
__global__ void k_ugen(const float* __restrict__ w) {
    int idx = blockIdx.x*256 + threadIdx.x;
    if (idx >= MID*MID) return;
    int co = idx & 127, ci = idx >> 7;
    float g[3][3];
    #pragma unroll
    for (int r = 0; r < 3; r++)
        #pragma unroll
        for (int c = 0; c < 3; c++)
            g[r][c] = w[((long)(co*MID + ci)*3 + r)*3 + c];
    float t[4][3];
    #pragma unroll
    for (int c = 0; c < 3; c++) {
        t[0][c] = g[0][c];
        t[1][c] = 0.5f*(g[0][c] + g[1][c] + g[2][c]);
        t[2][c] = 0.5f*(g[0][c] - g[1][c] + g[2][c]);
        t[3][c] = g[2][c];
    }
    float* out = g_U + (long)ci*16*MID + co;
    #pragma unroll
    for (int r = 0; r < 4; r++) {
        float u0 = t[r][0];
        float u1 = 0.5f*(t[r][0] + t[r][1] + t[r][2]);
        float u2 = 0.5f*(t[r][0] - t[r][1] + t[r][2]);
        float u3 = t[r][2];
        out[(r*4+0)*MID] = u0;
        out[(r*4+1)*MID] = u1;
        out[(r*4+2)*MID] = u2;
        out[(r*4+3)*MID] = u3;
    }
}

// ---------------- winograd input transform: V = B^T d B (with BN+ReLU) -----
// g_V layout: [n][ci][k][tile]; tile = ty*TP+tx, plane stride TP*TP
__global__ void k_vgen(int inbuf, int HI, int WI, int TP, long total) {
    long idx = (long)blockIdx.x*256 + threadIdx.x;
    if (idx >= total) return;
    long q = idx;
    int tx = (int)(q % TP); q /= TP;
    int ty = (int)(q % TP); q /= TP;
    int ci = (int)(q & 127);
    int n  = (int)(q >> 7);
    const float* in = getbuf(inbuf) + (long)(n*MID + ci)*HI*WI;
    float al = g_alpha[ci], be = g_beta[ci];

    float d[4][4];
    int iy0 = ty*2, ix0 = tx*2;
    #pragma unroll
    for (int r = 0; r < 4; r++) {
        int iy = iy0 + r;
        #pragma unroll
        for (int c = 0; c < 4; c++) {
            int ix = ix0 + c;
            float v = 0.f;
            if (iy < HI && ix < WI) v = in[iy*WI + ix];
            d[r][c] = fmaxf(fmaf(al, v, be), 0.f);
        }
    }
    // t = B^T d
    float t0[4], t1[4], t2[4], t3[4];
    #pragma unroll
    for (int c = 0; c < 4; c++) {
        t0[c] = d[0][c] - d[2][c];
        t1[c] = d[1][c] + d[2][c];
        t2[c] = d[2][c] - d[1][c];
        t3[c] = d[1][c] - d[3][c];
    }
    long TP2 = (long)TP*TP;
    float* out = g_V + ((long)(n*MID + ci)*16)*TP2 + (long)ty*TP + tx;
    float* rows[4] = {t0, t1, t2, t3};
    #pragma unroll
    for (int r = 0; r < 4; r++) {
        float* a = rows[r];
        out[(long)(r*4+0)*TP2] = a[0] - a[2];
        out[(long)(r*4+1)*TP2] = a[1] + a[2];
        out[(long)(r*4+2)*TP2] = a[2] - a[1];
        out[(long)(r*4+3)*TP2] = a[1] - a[3];
    }
}

// ---------------- winograd multiply + output transform (fp32) --------------
// block: 256 thr = 16 k-points x 16 workers; worker = 8co x 4tiles at one k.
// block tile: 16k x 32co x 16tiles (linear). 3-stage cp.async pipeline with
// the proven 2-barrier-per-chunk structure (wait -> bar -> compute -> bar).
// fp32 chunk accumulation (8 ci) + fp32 fold (16 chunks) -- identical to R11.
__global__ __launch_bounds__(256)
void k_wino(int HO, int WO, int TP, const float* __restrict__ bias) {
    extern __shared__ __align__(16) float sm[];   // 3 x 6144 floats = 72 KB

    int tid = threadIdx.x;
    int kk = tid >> 4, w = tid & 15, cb = w >> 2, tb = w & 3;
    int tg0 = blockIdx.y << 4;          // 16 tiles per block
    int n   = blockIdx.z;
    int co0 = blockIdx.x << 5;

    unsigned smb = (unsigned)__cvta_generic_to_shared(sm);
    long TP2 = (long)TP*TP;

    auto issue_chunk = [&](int c) {
        int ci0 = c*8;
        unsigned vb = smb + (unsigned)((c%3)*6144)*4u;
        unsigned ub = vb + 2048u*4u;
        // V: 8ci x 16k x 16tiles = 512 float4, 2/thread
        #pragma unroll
        for (int it = 0; it < 2; it++) {
            int u = tid + it*256;
            int f4 = u & 3, k = (u>>2)&15, ci = u>>6;
            const float* src = g_V + ((long)(n*MID + ci0+ci)*16 + k)*TP2
                                   + tg0 + f4*4;
            unsigned dst = vb + (unsigned)((ci*16+k)*16 + f4*4)*4u;
            asm volatile("cp.async.ca.shared.global [%0], [%1], 16;\n"
                         :: "r"(dst), "l"(src));
        }
        // U: 8ci x 16k x 32co = 1024 float4, 4/thread
        #pragma unroll
        for (int it = 0; it < 4; it++) {
            int u = tid + it*256;
            int f4 = u & 7, k = (u>>3)&15, ci = u>>7;
            const float* src = g_U + ((long)(ci0+ci)*16 + k)*MID + co0 + f4*4;
            unsigned dst = ub + (unsigned)((ci*16+k)*32 + f4*4)*4u;
            asm volatile("cp.async.ca.shared.global [%0], [%1], 16;\n"
                         :: "r"(dst), "l"(src));
        }
        asm volatile("cp.async.commit_group;\n");
    };

    float macc[8][4];
    #pragma unroll
    for (int i = 0; i < 8; i++)
        #pragma unroll
        for (int t = 0; t < 4; t++) macc[i][t] = 0.f;

    issue_chunk(0);
    issue_chunk(1);

    #pragma unroll 1
    for (int c = 0; c < 16; c++) {
        // issue into buf (c+2)%3 == (c-1)%3: safe — the trailing barrier of
        // iteration c-1 ordered all threads' compute(c-1) before this point.
        if (c <= 13) {
            issue_chunk(c + 2);
            asm volatile("cp.async.wait_group 2;\n");   // chunk c complete (own)
        } else if (c == 14) {
            asm volatile("cp.async.wait_group 1;\n");
        } else {
            asm volatile("cp.async.wait_group 0;\n");
        }
        __syncthreads();     // cross-thread visibility of chunk c

        const float* Vb = sm + (c%3)*6144;
        const float* Ub = Vb + 2048;

        float acc[8][4];
        #pragma unroll
        for (int i = 0; i < 8; i++)
            #pragma unroll
            for (int t = 0; t < 4; t++) acc[i][t] = 0.f;

        #pragma unroll
        for (int ci = 0; ci < 8; ci++) {
            float4 v  = *(const float4*)(Vb + (ci*16+kk)*16 + tb*4);
            float4 ua = *(const float4*)(Ub + (ci*16+kk)*32 + cb*8);
            float4 uc = *(const float4*)(Ub + (ci*16+kk)*32 + cb*8 + 4);
            float vv[4] = {v.x, v.y, v.z, v.w};
            float uu[8] = {ua.x, ua.y, ua.z, ua.w, uc.x, uc.y, uc.z, uc.w};
            #pragma unroll
            for (int i = 0; i < 8; i++)
                #pragma unroll
                for (int t = 0; t < 4; t++)
                    acc[i][t] = fmaf(uu[i], vv[t], acc[i][t]);
        }
        #pragma unroll
        for (int i = 0; i < 8; i++)
            #pragma unroll
            for (int t = 0; t < 4; t++) macc[i][t] += acc[i][t];

        __syncthreads();     // compute(c) done before buf (c)%3 is overwritten
    }

    // ---- epilogue: 2 passes over co halves; transpose via smem ----
    #pragma unroll
    for (int p = 0; p < 2; p++) {
        __syncthreads();
        if ((cb >> 1) == p) {
            int coh = (cb & 1)*8;
            #pragma unroll
            for (int i = 0; i < 8; i++)
                #pragma unroll
                for (int t = 0; t < 4; t++)
                    sm[kk*256 + (coh+i)*16 + tb*4 + t] = macc[i][t];
        }
        __syncthreads();

        int coL = tid >> 4;          // 0..15
        int til = tid & 15;
        float m[16];
        #pragma unroll
        for (int k = 0; k < 16; k++)
            m[k] = sm[k*256 + coL*16 + til];

        float t0[4], t1[4];
        #pragma unroll
        for (int c = 0; c < 4; c++) {
            t0[c] = m[c] + m[4+c] + m[8+c];
            t1[c] = m[4+c] - m[8+c] - m[12+c];
        }
        int co = co0 + p*16 + coL;
        float bv = bias[co];
        float y00 = t0[0] + t0[1] + t0[2] + bv;
        float y01 = t0[1] - t0[2] - t0[3] + bv;
        float y10 = t1[0] + t1[1] + t1[2] + bv;
        float y11 = t1[1] - t1[2] - t1[3] + bv;

        int tgl = tg0 + til;
        int ty = tgl / TP, tx = tgl - ty*TP;
        int oy = ty*2, ox = tx*2;
        float* out = g_conv + (long)(n*MID + co)*HO*WO;
        if (oy < HO) {
            if (ox   < WO) out[oy*WO + ox  ] = y00;
            if (ox+1 < WO) out[oy*WO + ox+1] = y01;
        }
        if (oy+1 < HO) {
            if (ox   < WO) out[(oy+1)*WO + ox  ] = y10;
            if (ox+1 < WO) out[(oy+1)*WO + ox+1] = y11;
        }
    }
}

// ---------------- maxpool 3x3 stride 2 (valid) ----------------
__global__ void k_pool(int outbuf, int HO, int WO, int HP, int WP) {
    const float* in = g_conv;
    float* out = getbuf(outbuf);
    long idx = (long)blockIdx.x * 256 + threadIdx.x;
    long total = (long)BN * MID * HP * WP;
    if (idx >= total) return;
    int wp = (int)(idx % WP); long t = idx / WP;
    int hp = (int)(t % HP);   t /= HP;        // t = n*128 + c
    const float* base = in + t * (long)HO * WO + (long)(hp*2) * WO + wp*2;
    float m = -3.4e38f;
    #pragma unroll
    for (int a = 0; a < 3; a++)
        #pragma unroll
        for (int b2 = 0; b2 < 3; b2++)
            m = fmaxf(m, base[a*WO + b2]);
    out[idx] = m;
}

// ---------------- LRN (size=128 channel window) after BN+ReLU, fp64 --------
__global__ void k_lrn(int inbuf) {
    const float* in = getbuf(inbuf);
    int blk = blockIdx.x;
    int n = blk >> 4, hw = blk & 15;
    int c = threadIdx.x;
    __shared__ double sq[MID];
    float vf = in[(((long)n*MID + c) * 16) + hw];
    double v = fmax(fma((double)g_alpha[c], (double)vf, (double)g_beta[c]), 0.0);
    sq[c] = v * v;
    __syncthreads();
    int lo = c - 64 < 0 ? 0 : c - 64;
    int hi = c + 63 > 127 ? 127 : c + 63;
    double wsum = 0.0;
    for (int j = lo; j <= hi; j++) wsum += sq[j];
    double base = 1.0 + 1e-4 * (wsum / 128.0);
    g_feat[n*2048 + c*16 + hw] = (float)(v * pow(base, -0.75));
}

// ---------------- linear: reg = feat @ Wr^T + br  (fp64 accum) -------------
__global__ void k_linear(const float* __restrict__ Wr, const float* __restrict__ br) {
    int j = blockIdx.x % 7, n = blockIdx.x / 7;
    const float* f  = g_feat + n*2048;
    const float* wr = Wr + j*2048;
    double s = 0.0;
    for (int k = threadIdx.x; k < 2048; k += 32)
        s += (double)f[k] * (double)wr[k];
    #pragma unroll
    for (int o = 16; o > 0; o >>= 1)
        s += __shfl_down_sync(0xffffffffu, s, o);
    if (threadIdx.x == 0) g_reg[n*7 + j] = s + (double)br[j];
}

// ---------------- spectral normalize (sequential scan, fp64) + sigmoid -----
__global__ void k_spectral(const float* __restrict__ u0, const float* __restrict__ v0) {
    double u[2] = {(double)u0[0], (double)u0[1]};
    double v[3] = {(double)v0[0], (double)v0[1], (double)v0[2]};
    for (int n = 0; n < BN; n++) {
        double W[6];
        #pragma unroll
        for (int i = 0; i < 6; i++) W[i] = g_reg[n*7 + i];
        for (int it = 0; it < 4; it++) {
            double nv0 = W[0]*u[0] + W[3]*u[1];
            double nv1 = W[1]*u[0] + W[4]*u[1];
            double nv2 = W[2]*u[0] + W[5]*u[1];
            double nn = sqrt(nv0*nv0 + nv1*nv1 + nv2*nv2);
            nn = fmax(nn, 1e-12);
            v[0] = nv0/nn; v[1] = nv1/nn; v[2] = nv2/nn;
            double nu0 = W[0]*v[0] + W[1]*v[1] + W[2]*v[2];
            double nu1 = W[3]*v[0] + W[4]*v[1] + W[5]*v[2];
            nn = sqrt(nu0*nu0 + nu1*nu1);
            nn = fmax(nn, 1e-12);
            u[0] = nu0/nn; u[1] = nu1/nn;
        }
        double Wv0 = W[0]*v[0] + W[1]*v[1] + W[2]*v[2];
        double Wv1 = W[3]*v[0] + W[4]*v[1] + W[5]*v[2];
        double sigma = u[0]*Wv0 + u[1]*Wv1;
        #pragma unroll
        for (int i = 0; i < 6; i++) g_theta[n*6 + i] = W[i] / sigma;
        g_m[n] = 1.0 / (1.0 + exp(-g_reg[n*7 + 6]));
    }
}

// ---------------- affine grid + reflect bilinear sample + scale ------------
__device__ __forceinline__ double reflect_d(double x, double size) {
    double r = fabs(x + 0.5);
    r = fmod(r, 2.0 * size);
    if (r > size) r = 2.0 * size - r;
    r = r - 0.5;
    return fmin(fmax(r, 0.0), size - 1.0);
}

__global__ void k_sample(const float* __restrict__ x, float* __restrict__ out) {
    long idx = (long)blockIdx.x * 256 + threadIdx.x;    // over N*H*W
    if (idx >= (long)BN * HW0) return;
    int w = (int)(idx % WIN); long t = idx / WIN;
    int h = (int)(t % HIN);
    int n = (int)(t / HIN);

    const double* th = g_theta + n*6;
    double gx = (2.0*w + 1.0) / (double)WIN - 1.0;
    double gy = (2.0*h + 1.0) / (double)HIN - 1.0;
    double px = th[0]*gx + th[1]*gy + th[2];
    double py = th[3]*gx + th[4]*gy + th[5];

    double ix = reflect_d(((px + 1.0) * (double)WIN - 1.0) * 0.5, (double)WIN);
    double iy = reflect_d(((py + 1.0) * (double)HIN - 1.0) * 0.5, (double)HIN);

    double x0f = floor(ix), y0f = floor(iy);
    double wx = ix - x0f, wy = iy - y0f;
    int x0i = min(max((int)x0f, 0), WIN-1);
    int y0i = min(max((int)y0f, 0), HIN-1);
    int x1i = min(max((int)x0f + 1, 0), WIN-1);
    int y1i = min(max((int)y0f + 1, 0), HIN-1);

    double w00 = (1.0-wx)*(1.0-wy), w01 = wx*(1.0-wy);
    double w10 = (1.0-wx)*wy,       w11 = wx*wy;
    double mm = g_m[n];

    const float* xb = x   + (long)n*CIN*HW0;
    float*       ob = out + (long)n*CIN*HW0 + (long)h*WIN + w;
    int o00 = y0i*WIN + x0i, o01 = y0i*WIN + x1i;
    int o10 = y1i*WIN + x0i, o11 = y1i*WIN + x1i;
    for (int c = 0; c < CIN; c++) {
        const float* xc = xb + (long)c*HW0;
        double v = (double)xc[o00]*w00 + (double)xc[o01]*w01
                 + (double)xc[o10]*w10 + (double)xc[o11]*w11;
        ob[(long)c*HW0] = (float)(v * mm);
    }
}

// ---------------- host orchestration ----------------
extern "C" void kernel_launch(void* const* d_in, const int* in_sizes, int n_in,
                              void* d_out, int out_size) {
    const float* x       = (const float*)d_in[0];
    const float* conv0_w = (const float*)d_in[1];
    const float* conv0_b = (const float*)d_in[2];
    const float* convs_w = (const float*)d_in[3];
    const float* convs_b = (const float*)d_in[4];
    const float* bn_g    = (const float*)d_in[5];
    const float* bn_b    = (const float*)d_in[6];
    const float* Wr      = (const float*)d_in[7];
    const float* br      = (const float*)d_in[8];
    const float* u0      = (const float*)d_in[9];
    const float* v0      = (const float*)d_in[10];
    float* out = (float*)d_out;

    // allow 72 KB dynamic smem for k_wino (host-side attr, capture-safe)
    cudaFuncSetAttribute(k_wino, cudaFuncAttributeMaxDynamicSharedMemorySize, 73728);

    // conv0 (1x1) -> g_act0 (buf 0)
    k_conv0<<<(BN*HW0/4 + 255)/256, 256>>>(x, conv0_w, conv0_b);
    // bn0 stats on conv0 output (8-way split + deterministic finalize)
    k_bn_part<<<1024, 256>>>(0, HW0);
    k_bn_fin<<<1, 128>>>(HW0, bn_g + 0*MID, bn_b + 0*MID);

    struct Stage { int inbuf, outbuf, HI, HO, HP, TP; };
    const Stage st[5] = {
        {0, 2, 224, 222, 110, 112},
        {2, 3, 110, 108,  53,  56},
        {3, 2,  53,  51,  25,  28},
        {2, 3,  25,  23,  11,  12},
        {3, 2,  11,   9,   4,   8},
    };

    for (int s = 0; s < 5; s++) {
        int HI = st[s].HI, HO = st[s].HO, HP = st[s].HP, TP = st[s].TP;
        // weight transform
        k_ugen<<<(MID*MID + 255)/256, 256>>>(convs_w + (size_t)s*MID*MID*9);
        // input transform (fused BN+ReLU)
        long vtotal = (long)BN * MID * TP * TP;
        k_vgen<<<(unsigned)((vtotal + 255)/256), 256>>>(st[s].inbuf, HI, HI, TP, vtotal);
        // winograd multiply + output transform -> g_conv
        dim3 wgrid(4, (TP*TP)/16, BN);
        k_wino<<<wgrid, 256, 73728>>>(HO, HO, TP, convs_b + s*MID);
        // maxpool + next BN stats
        long ptotal = (long)BN*MID*HP*HP;
        k_pool<<<(unsigned)((ptotal + 255)/256), 256>>>(st[s].outbuf, HO, HO, HP, HP);
        k_bn_part<<<1024, 256>>>(st[s].outbuf, HP*HP);
        k_bn_fin<<<1, 128>>>(HP*HP, bn_g + (s+1)*MID, bn_b + (s+1)*MID);
    }

    // LRN on final pooled (buf 2 = g_pa, 16x128x4x4) with bn5 transform
    k_lrn<<<BN*16, MID>>>(2);
    // linear -> reg
    k_linear<<<BN*7, 32>>>(Wr, br);
    // spectral norm scan + m
    k_spectral<<<1, 1>>>(u0, v0);
    // sample
    k_sample<<<(unsigned)(((long)BN*HW0 + 255)/256), 256>>>(x, out);
}

// round 14
// speedup vs baseline: 1.0807x; 1.0264x over previous
#include <cuda_runtime.h>
#include <cuda_bf16.h>
#include <math.h>

// ---------------- problem constants ----------------
#define BN     16      // batch
#define CIN    16      // input channels
#define HIN    224
#define WIN    224
#define MID    128
#define HW0    (HIN*WIN)   // 50176

// ---------------- scratch (device globals; no allocation) ----------------
__device__ float g_act0[(size_t)BN*MID*224*224];   // conv0 raw output
__device__ float g_conv[(size_t)BN*MID*222*222];   // conv3x3 raw output (max size)
__device__ float g_pa  [(size_t)BN*MID*110*110];   // pooled ping
__device__ float g_pb  [(size_t)BN*MID*53*53];     // pooled pong
__device__ float g_V   [(size_t)BN*MID*16*12544];  // winograd V, [n][ci][k][tile]
__device__ float g_U   [5*MID*16*MID];             // winograd U, [stage][ci][k][co]
__device__ float  g_alpha[MID];
__device__ float  g_beta [MID];
__device__ double g_bnp [MID*8*2];                 // BN partial sums
__device__ float  g_feat[BN*2048];
__device__ double g_reg [BN*7];
__device__ double g_theta[BN*6];
__device__ double g_m[BN];

__device__ __forceinline__ float* getbuf(int s) {
    switch (s) {
        case 0: return g_act0;
        case 1: return g_conv;
        case 2: return g_pa;
        default: return g_pb;
    }
}

// ---------------- conv0: 1x1, 16 -> 128 ----------------
__global__ __launch_bounds__(256) void k_conv0(const float* __restrict__ x,
                                               const float* __restrict__ w,
                                               const float* __restrict__ b) {
    __shared__ float ws[MID*CIN];
    __shared__ float bs[MID];
    int tid = threadIdx.x;
    for (int i = tid; i < MID*CIN; i += 256) ws[i] = w[i];
    if (tid < MID) bs[tid] = b[tid];
    __syncthreads();

    long gid = (long)blockIdx.x * 256 + tid;             // pixel-group id
    int n  = (int)(gid / (HW0/4));
    int pg = (int)(gid % (HW0/4));
    int p  = pg * 4;

    const float* xp = x + (long)n*CIN*HW0 + p;
    float4 v[CIN];
    #pragma unroll
    for (int ci = 0; ci < CIN; ci++)
        v[ci] = *(const float4*)(xp + (long)ci*HW0);

    float* op = g_act0 + (long)n*MID*HW0 + p;
    for (int co = 0; co < MID; co++) {
        float4 a; a.x = a.y = a.z = a.w = bs[co];
        #pragma unroll
        for (int ci = 0; ci < CIN; ci++) {
            float wv = ws[co*CIN + ci];
            a.x = fmaf(v[ci].x, wv, a.x);
            a.y = fmaf(v[ci].y, wv, a.y);
            a.z = fmaf(v[ci].z, wv, a.z);
            a.w = fmaf(v[ci].w, wv, a.w);
        }
        *(float4*)(op + (long)co*HW0) = a;
    }
}

// ---------------- BN stats: 8-way split partials + fixed-order finalize -----
// (used for conv0 output only; conv stages use the fused pool+bn kernel)
__global__ void k_bn_part(int inbuf, int HWp) {
    int c = blockIdx.x & 127;
    int p = blockIdx.x >> 7;                 // 0..7 -> images [2p, 2p+2)
    const float* base0 = getbuf(inbuf);
    int tid = threadIdx.x;
    double s = 0.0, ss = 0.0;
    for (int n = p*2; n < p*2 + 2; n++) {
        const float* base = base0 + ((long)n*MID + c) * HWp;
        for (int i = tid; i < HWp; i += 256) {
            double v = (double)base[i];
            s += v; ss += v*v;
        }
    }
    __shared__ double sh[256], sh2[256];
    sh[tid] = s; sh2[tid] = ss;
    __syncthreads();
    for (int k = 128; k > 0; k >>= 1) {
        if (tid < k) { sh[tid] += sh[tid+k]; sh2[tid] += sh2[tid+k]; }
        __syncthreads();
    }
    if (tid == 0) {
        g_bnp[(c*8 + p)*2    ] = sh[0];
        g_bnp[(c*8 + p)*2 + 1] = sh2[0];
    }
}

__global__ void k_bn_fin(int HWp, const float* __restrict__ g,
                         const float* __restrict__ b) {
    int c = threadIdx.x;                     // 128 threads
    double s = 0.0, ss = 0.0;
    for (int p = 0; p < 8; p++) {            // fixed order -> deterministic
        s  += g_bnp[(c*8 + p)*2];
        ss += g_bnp[(c*8 + p)*2 + 1];
    }
    double M   = (double)BN * (double)HWp;
    double mu  = s / M;
    double var = ss / M - mu*mu;
    double a   = (double)g[c] / sqrt(var + 1e-5);
    g_alpha[c] = (float)a;
    g_beta[c]  = (float)((double)b[c] - mu*a);
}

// ---------------- winograd weight transform, all 5 stages -------------------
// g_U layout: [stage][ci][k][co]
__global__ void k_ugen(const float* __restrict__ w_all) {
    int idx = blockIdx.x*256 + threadIdx.x;
    if (idx >= 5*MID*MID) return;
    int st = idx >> 14;                        // /16384
    int rem = idx & 16383;
    int co = rem & 127, ci = rem >> 7;
    const float* w = w_all + (size_t)st*MID*MID*9;
    float g[3][3];
    #pragma unroll
    for (int r = 0; r < 3; r++)
        #pragma unroll
        for (int c = 0; c < 3; c++)
            g[r][c] = w[((long)(co*MID + ci)*3 + r)*3 + c];
    float t[4][3];
    #pragma unroll
    for (int c = 0; c < 3; c++) {
        t[0][c] = g[0][c];
        t[1][c] = 0.5f*(g[0][c] + g[1][c] + g[2][c]);
        t[2][c] = 0.5f*(g[0][c] - g[1][c] + g[2][c]);
        t[3][c] = g[2][c];
    }
    float* out = g_U + ((long)st*MID + ci)*16*MID + co;
    #pragma unroll
    for (int r = 0; r < 4; r++) {
        float u0 = t[r][0];
        float u1 = 0.5f*(t[r][0] + t[r][1] + t[r][2]);
        float u2 = 0.5f*(t[r][0] - t[r][1] + t[r][2]);
        float u3 = t[r][2];
        out[(r*4+0)*MID] = u0;
        out[(r*4+1)*MID] = u1;
        out[(r*4+2)*MID] = u2;
        out[(r*4+3)*MID] = u3;
    }
}

// ---------------- winograd input transform: V = B^T d B (with BN+ReLU) -----
// g_V layout: [n][ci][k][tile]; tile = ty*TP+tx, plane stride TP*TP
__global__ void k_vgen(int inbuf, int HI, int WI, int TP, long total) {
    long idx = (long)blockIdx.x*256 + threadIdx.x;
    if (idx >= total) return;
    long q = idx;
    int tx = (int)(q % TP); q /= TP;
    int ty = (int)(q % TP); q /= TP;
    int ci = (int)(q & 127);
    int n  = (int)(q >> 7);
    const float* in = getbuf(inbuf) + (long)(n*MID + ci)*HI*WI;
    float al = g_alpha[ci], be = g_beta[ci];

    float d[4][4];
    int iy0 = ty*2, ix0 = tx*2;
    #pragma unroll
    for (int r = 0; r < 4; r++) {
        int iy = iy0 + r;
        #pragma unroll
        for (int c = 0; c < 4; c++) {
            int ix = ix0 + c;
            float v = 0.f;
            if (iy < HI && ix < WI) v = in[iy*WI + ix];
            d[r][c] = fmaxf(fmaf(al, v, be), 0.f);
        }
    }
    // t = B^T d
    float t0[4], t1[4], t2[4], t3[4];
    #pragma unroll
    for (int c = 0; c < 4; c++) {
        t0[c] = d[0][c] - d[2][c];
        t1[c] = d[1][c] + d[2][c];
        t2[c] = d[2][c] - d[1][c];
        t3[c] = d[1][c] - d[3][c];
    }
    long TP2 = (long)TP*TP;
    float* out = g_V + ((long)(n*MID + ci)*16)*TP2 + (long)ty*TP + tx;
    float* rows[4] = {t0, t1, t2, t3};
    #pragma unroll
    for (int r = 0; r < 4; r++) {
        float* a = rows[r];
        out[(long)(r*4+0)*TP2] = a[0] - a[2];
        out[(long)(r*4+1)*TP2] = a[1] + a[2];
        out[(long)(r*4+2)*TP2] = a[2] - a[1];
        out[(long)(r*4+3)*TP2] = a[1] - a[3];
    }
}

// ---------------- winograd multiply + output transform (fp32) --------------
// block: 256 thr = 16 k-points x 16 workers; worker = 8co x 4tiles at one k.
// block tile: 16k x 32co x 16tiles (linear). 3-stage cp.async pipeline with
// the proven 2-barrier-per-chunk structure (wait -> bar -> compute -> bar).
// fp32 chunk accumulation (8 ci) + fp32 fold (16 chunks) -- identical to R11.
__global__ __launch_bounds__(256)
void k_wino(int HO, int WO, int TP, int stage, const float* __restrict__ bias) {
    extern __shared__ __align__(16) float sm[];   // 3 x 6144 floats = 72 KB

    int tid = threadIdx.x;
    int kk = tid >> 4, w = tid & 15, cb = w >> 2, tb = w & 3;
    int tg0 = blockIdx.y << 4;          // 16 tiles per block
    int n   = blockIdx.z;
    int co0 = blockIdx.x << 5;

    unsigned smb = (unsigned)__cvta_generic_to_shared(sm);
    long TP2 = (long)TP*TP;
    const float* Ubase = g_U + (long)stage*MID*16*MID;

    auto issue_chunk = [&](int c) {
        int ci0 = c*8;
        unsigned vb = smb + (unsigned)((c%3)*6144)*4u;
        unsigned ub = vb + 2048u*4u;
        // V: 8ci x 16k x 16tiles = 512 float4, 2/thread
        #pragma unroll
        for (int it = 0; it < 2; it++) {
            int u = tid + it*256;
            int f4 = u & 3, k = (u>>2)&15, ci = u>>6;
            const float* src = g_V + ((long)(n*MID + ci0+ci)*16 + k)*TP2
                                   + tg0 + f4*4;
            unsigned dst = vb + (unsigned)((ci*16+k)*16 + f4*4)*4u;
            asm volatile("cp.async.ca.shared.global [%0], [%1], 16;\n"
                         :: "r"(dst), "l"(src));
        }
        // U: 8ci x 16k x 32co = 1024 float4, 4/thread
        #pragma unroll
        for (int it = 0; it < 4; it++) {
            int u = tid + it*256;
            int f4 = u & 7, k = (u>>3)&15, ci = u>>7;
            const float* src = Ubase + ((long)(ci0+ci)*16 + k)*MID + co0 + f4*4;
            unsigned dst = ub + (unsigned)((ci*16+k)*32 + f4*4)*4u;
            asm volatile("cp.async.ca.shared.global [%0], [%1], 16;\n"
                         :: "r"(dst), "l"(src));
        }
        asm volatile("cp.async.commit_group;\n");
    };

    float macc[8][4];
    #pragma unroll
    for (int i = 0; i < 8; i++)
        #pragma unroll
        for (int t = 0; t < 4; t++) macc[i][t] = 0.f;

    issue_chunk(0);
    issue_chunk(1);

    #pragma unroll 1
    for (int c = 0; c < 16; c++) {
        // issue into buf (c+2)%3 == (c-1)%3: safe — the trailing barrier of
        // iteration c-1 ordered all threads' compute(c-1) before this point.
        if (c <= 13) {
            issue_chunk(c + 2);
            asm volatile("cp.async.wait_group 2;\n");   // chunk c complete (own)
        } else if (c == 14) {
            asm volatile("cp.async.wait_group 1;\n");
        } else {
            asm volatile("cp.async.wait_group 0;\n");
        }
        __syncthreads();     // cross-thread visibility of chunk c

        const float* Vb = sm + (c%3)*6144;
        const float* Ub = Vb + 2048;

        float acc[8][4];
        #pragma unroll
        for (int i = 0; i < 8; i++)
            #pragma unroll
            for (int t = 0; t < 4; t++) acc[i][t] = 0.f;

        #pragma unroll
        for (int ci = 0; ci < 8; ci++) {
            float4 v  = *(const float4*)(Vb + (ci*16+kk)*16 + tb*4);
            float4 ua = *(const float4*)(Ub + (ci*16+kk)*32 + cb*8);
            float4 uc = *(const float4*)(Ub + (ci*16+kk)*32 + cb*8 + 4);
            float vv[4] = {v.x, v.y, v.z, v.w};
            float uu[8] = {ua.x, ua.y, ua.z, ua.w, uc.x, uc.y, uc.z, uc.w};
            #pragma unroll
            for (int i = 0; i < 8; i++)
                #pragma unroll
                for (int t = 0; t < 4; t++)
                    acc[i][t] = fmaf(uu[i], vv[t], acc[i][t]);
        }
        #pragma unroll
        for (int i = 0; i < 8; i++)
            #pragma unroll
            for (int t = 0; t < 4; t++) macc[i][t] += acc[i][t];

        __syncthreads();     // compute(c) done before buf (c)%3 is overwritten
    }

    // ---- epilogue: 2 passes over co halves; transpose via smem ----
    #pragma unroll
    for (int p = 0; p < 2; p++) {
        __syncthreads();
        if ((cb >> 1) == p) {
            int coh = (cb & 1)*8;
            #pragma unroll
            for (int i = 0; i < 8; i++)
                #pragma unroll
                for (int t = 0; t < 4; t++)
                    sm[kk*256 + (coh+i)*16 + tb*4 + t] = macc[i][t];
        }
        __syncthreads();

        int coL = tid >> 4;          // 0..15
        int til = tid & 15;
        float m[16];
        #pragma unroll
        for (int k = 0; k < 16; k++)
            m[k] = sm[k*256 + coL*16 + til];

        float t0[4], t1[4];
        #pragma unroll
        for (int c = 0; c < 4; c++) {
            t0[c] = m[c] + m[4+c] + m[8+c];
            t1[c] = m[4+c] - m[8+c] - m[12+c];
        }
        int co = co0 + p*16 + coL;
        float bv = bias[co];
        float y00 = t0[0] + t0[1] + t0[2] + bv;
        float y01 = t0[1] - t0[2] - t0[3] + bv;
        float y10 = t1[0] + t1[1] + t1[2] + bv;
        float y11 = t1[1] - t1[2] - t1[3] + bv;

        int tgl = tg0 + til;
        int ty = tgl / TP, tx = tgl - ty*TP;
        int oy = ty*2, ox = tx*2;
        float* out = g_conv + (long)(n*MID + co)*HO*WO;
        if (oy < HO) {
            if (ox   < WO) out[oy*WO + ox  ] = y00;
            if (ox+1 < WO) out[oy*WO + ox+1] = y01;
        }
        if (oy+1 < HO) {
            if (ox   < WO) out[(oy+1)*WO + ox  ] = y10;
            if (ox+1 < WO) out[(oy+1)*WO + ox+1] = y11;
        }
    }
}

// ---------------- fused maxpool 3x3 s2 + BN partial sums -------------------
// grid: 1024 blocks = (c 0..127, p 0..7); block pools 2 images' planes and
// accumulates fp64 partials in the SAME per-thread order as the old k_bn_part
// (n in pair, i strided by 256) -> g_bnp bitwise identical.
__global__ void k_poolbn(int outbuf, int HO, int WO, int HP, int WP) {
    int c = blockIdx.x & 127;
    int p = blockIdx.x >> 7;
    float* out = getbuf(outbuf);
    int tid = threadIdx.x;
    int HWp = HP*WP;
    double s = 0.0, ss = 0.0;
    for (int n = p*2; n < p*2 + 2; n++) {
        const float* base = g_conv + ((long)n*MID + c)*HO*WO;
        float* ob = out + ((long)n*MID + c)*HWp;
        for (int i = tid; i < HWp; i += 256) {
            int hp = i / WP, wp = i - hp*WP;
            const float* bp = base + (long)(hp*2)*WO + wp*2;
            float m = -3.4e38f;
            #pragma unroll
            for (int a = 0; a < 3; a++)
                #pragma unroll
                for (int b2 = 0; b2 < 3; b2++)
                    m = fmaxf(m, bp[a*WO + b2]);
            ob[i] = m;
            double v = (double)m;
            s += v; ss += v*v;
        }
    }
    __shared__ double sh[256], sh2[256];
    sh[tid] = s; sh2[tid] = ss;
    __syncthreads();
    for (int k = 128; k > 0; k >>= 1) {
        if (tid < k) { sh[tid] += sh[tid+k]; sh2[tid] += sh2[tid+k]; }
        __syncthreads();
    }
    if (tid == 0) {
        g_bnp[(c*8 + p)*2    ] = sh[0];
        g_bnp[(c*8 + p)*2 + 1] = sh2[0];
    }
}

// ---------------- LRN (size=128 channel window) after BN+ReLU, fp64 --------
__global__ void k_lrn(int inbuf) {
    const float* in = getbuf(inbuf);
    int blk = blockIdx.x;
    int n = blk >> 4, hw = blk & 15;
    int c = threadIdx.x;
    __shared__ double sq[MID];
    float vf = in[(((long)n*MID + c) * 16) + hw];
    double v = fmax(fma((double)g_alpha[c], (double)vf, (double)g_beta[c]), 0.0);
    sq[c] = v * v;
    __syncthreads();
    int lo = c - 64 < 0 ? 0 : c - 64;
    int hi = c + 63 > 127 ? 127 : c + 63;
    double wsum = 0.0;
    for (int j = lo; j <= hi; j++) wsum += sq[j];
    double base = 1.0 + 1e-4 * (wsum / 128.0);
    g_feat[n*2048 + c*16 + hw] = (float)(v * pow(base, -0.75));
}

// ---------------- linear: reg = feat @ Wr^T + br  (fp64 accum) -------------
__global__ void k_linear(const float* __restrict__ Wr, const float* __restrict__ br) {
    int j = blockIdx.x % 7, n = blockIdx.x / 7;
    const float* f  = g_feat + n*2048;
    const float* wr = Wr + j*2048;
    double s = 0.0;
    for (int k = threadIdx.x; k < 2048; k += 32)
        s += (double)f[k] * (double)wr[k];
    #pragma unroll
    for (int o = 16; o > 0; o >>= 1)
        s += __shfl_down_sync(0xffffffffu, s, o);
    if (threadIdx.x == 0) g_reg[n*7 + j] = s + (double)br[j];
}

// ---------------- spectral normalize (sequential scan, fp64) + sigmoid -----
__global__ void k_spectral(const float* __restrict__ u0, const float* __restrict__ v0) {
    double u[2] = {(double)u0[0], (double)u0[1]};
    double v[3] = {(double)v0[0], (double)v0[1], (double)v0[2]};
    for (int n = 0; n < BN; n++) {
        double W[6];
        #pragma unroll
        for (int i = 0; i < 6; i++) W[i] = g_reg[n*7 + i];
        for (int it = 0; it < 4; it++) {
            double nv0 = W[0]*u[0] + W[3]*u[1];
            double nv1 = W[1]*u[0] + W[4]*u[1];
            double nv2 = W[2]*u[0] + W[5]*u[1];
            double nn = sqrt(nv0*nv0 + nv1*nv1 + nv2*nv2);
            nn = fmax(nn, 1e-12);
            v[0] = nv0/nn; v[1] = nv1/nn; v[2] = nv2/nn;
            double nu0 = W[0]*v[0] + W[1]*v[1] + W[2]*v[2];
            double nu1 = W[3]*v[0] + W[4]*v[1] + W[5]*v[2];
            nn = sqrt(nu0*nu0 + nu1*nu1);
            nn = fmax(nn, 1e-12);
            u[0] = nu0/nn; u[1] = nu1/nn;
        }
        double Wv0 = W[0]*v[0] + W[1]*v[1] + W[2]*v[2];
        double Wv1 = W[3]*v[0] + W[4]*v[1] + W[5]*v[2];
        double sigma = u[0]*Wv0 + u[1]*Wv1;
        #pragma unroll
        for (int i = 0; i < 6; i++) g_theta[n*6 + i] = W[i] / sigma;
        g_m[n] = 1.0 / (1.0 + exp(-g_reg[n*7 + 6]));
    }
}

// ---------------- affine grid + reflect bilinear sample + scale ------------
__device__ __forceinline__ double reflect_d(double x, double size) {
    double r = fabs(x + 0.5);
    r = fmod(r, 2.0 * size);
    if (r > size) r = 2.0 * size - r;
    r = r - 0.5;
    return fmin(fmax(r, 0.0), size - 1.0);
}

__global__ void k_sample(const float* __restrict__ x, float* __restrict__ out) {
    long idx = (long)blockIdx.x * 256 + threadIdx.x;    // over N*H*W
    if (idx >= (long)BN * HW0) return;
    int w = (int)(idx % WIN); long t = idx / WIN;
    int h = (int)(t % HIN);
    int n = (int)(t / HIN);

    const double* th = g_theta + n*6;
    double gx = (2.0*w + 1.0) / (double)WIN - 1.0;
    double gy = (2.0*h + 1.0) / (double)HIN - 1.0;
    double px = th[0]*gx + th[1]*gy + th[2];
    double py = th[3]*gx + th[4]*gy + th[5];

    double ix = reflect_d(((px + 1.0) * (double)WIN - 1.0) * 0.5, (double)WIN);
    double iy = reflect_d(((py + 1.0) * (double)HIN - 1.0) * 0.5, (double)HIN);

    double x0f = floor(ix), y0f = floor(iy);
    double wx = ix - x0f, wy = iy - y0f;
    int x0i = min(max((int)x0f, 0), WIN-1);
    int y0i = min(max((int)y0f, 0), HIN-1);
    int x1i = min(max((int)x0f + 1, 0), WIN-1);
    int y1i = min(max((int)y0f + 1, 0), HIN-1);

    double w00 = (1.0-wx)*(1.0-wy), w01 = wx*(1.0-wy);
    double w10 = (1.0-wx)*wy,       w11 = wx*wy;
    double mm = g_m[n];

    const float* xb = x   + (long)n*CIN*HW0;
    float*       ob = out + (long)n*CIN*HW0 + (long)h*WIN + w;
    int o00 = y0i*WIN + x0i, o01 = y0i*WIN + x1i;
    int o10 = y1i*WIN + x0i, o11 = y1i*WIN + x1i;
    for (int c = 0; c < CIN; c++) {
        const float* xc = xb + (long)c*HW0;
        double v = (double)xc[o00]*w00 + (double)xc[o01]*w01
                 + (double)xc[o10]*w10 + (double)xc[o11]*w11;
        ob[(long)c*HW0] = (float)(v * mm);
    }
}

// ---------------- host orchestration ----------------
extern "C" void kernel_launch(void* const* d_in, const int* in_sizes, int n_in,
                              void* d_out, int out_size) {
    const float* x       = (const float*)d_in[0];
    const float* conv0_w = (const float*)d_in[1];
    const float* conv0_b = (const float*)d_in[2];
    const float* convs_w = (const float*)d_in[3];
    const float* convs_b = (const float*)d_in[4];
    const float* bn_g    = (const float*)d_in[5];
    const float* bn_b    = (const float*)d_in[6];
    const float* Wr      = (const float*)d_in[7];
    const float* br      = (const float*)d_in[8];
    const float* u0      = (const float*)d_in[9];
    const float* v0      = (const float*)d_in[10];
    float* out = (float*)d_out;

    // allow 72 KB dynamic smem for k_wino (host-side attr, capture-safe)
    cudaFuncSetAttribute(k_wino, cudaFuncAttributeMaxDynamicSharedMemorySize, 73728);

    // all 5 weight transforms up front (independent of activations)
    k_ugen<<<(5*MID*MID + 255)/256, 256>>>(convs_w);

    // conv0 (1x1) -> g_act0 (buf 0)
    k_conv0<<<(BN*HW0/4 + 255)/256, 256>>>(x, conv0_w, conv0_b);
    // bn0 stats on conv0 output (8-way split + deterministic finalize)
    k_bn_part<<<1024, 256>>>(0, HW0);
    k_bn_fin<<<1, 128>>>(HW0, bn_g + 0*MID, bn_b + 0*MID);

    struct Stage { int inbuf, outbuf, HI, HO, HP, TP; };
    const Stage st[5] = {
        {0, 2, 224, 222, 110, 112},
        {2, 3, 110, 108,  53,  56},
        {3, 2,  53,  51,  25,  28},
        {2, 3,  25,  23,  11,  12},
        {3, 2,  11,   9,   4,   8},
    };

    for (int s = 0; s < 5; s++) {
        int HI = st[s].HI, HO = st[s].HO, HP = st[s].HP, TP = st[s].TP;
        // input transform (fused BN+ReLU)
        long vtotal = (long)BN * MID * TP * TP;
        k_vgen<<<(unsigned)((vtotal + 255)/256), 256>>>(st[s].inbuf, HI, HI, TP, vtotal);
        // winograd multiply + output transform -> g_conv
        dim3 wgrid(4, (TP*TP)/16, BN);
        k_wino<<<wgrid, 256, 73728>>>(HO, HO, TP, s, convs_b + s*MID);
        // fused maxpool + BN partials, then deterministic finalize
        k_poolbn<<<1024, 256>>>(st[s].outbuf, HO, HO, HP, HP);
        k_bn_fin<<<1, 128>>>(HP*HP, bn_g + (s+1)*MID, bn_b + (s+1)*MID);
    }

    // LRN on final pooled (buf 2 = g_pa, 16x128x4x4) with bn5 transform
    k_lrn<<<BN*16, MID>>>(2);
    // linear -> reg
    k_linear<<<BN*7, 32>>>(Wr, br);
    // spectral norm scan + m
    k_spectral<<<1, 1>>>(u0, v0);
    // sample
    k_sample<<<(unsigned)(((long)BN*HW0 + 255)/256), 256>>>(x, out);
}